// round 2
// baseline (speedup 1.0000x reference)
#include <cuda_runtime.h>
#include <cstdint>

// Problem constants (fixed shapes per reference setup_inputs)
constexpr int N = 4096;
constexpr int K = 256;
constexpr float MARGIN = 0.3f;
constexpr float BIG = 10000.0f;

// GEMM tiling
constexpr int BM = 128, BN = 128, BK = 16, TM = 8, TN = 8;
// 256 threads: tx in [0,16), ty in [0,16)

// Scratch (device globals; no allocation allowed)
__device__ float    g_sq[N];
__device__ unsigned g_max_eq[N];   // float bits, nonneg => uint-ordered
__device__ unsigned g_min_gt[N];
__device__ unsigned g_min_lt[N];
__device__ int      g_label_cnt[8];

__global__ void k_init_counts() {
    if (threadIdx.x < 8) g_label_cnt[threadIdx.x] = 0;
}

// One warp per row: row norms, per-row stat init, label histogram.
__global__ void k_sq(const float* __restrict__ X, const int* __restrict__ T) {
    int warp = threadIdx.x >> 5, lane = threadIdx.x & 31;
    int row = blockIdx.x * 8 + warp;
    if (row >= N) return;
    const float4* p = reinterpret_cast<const float4*>(X + (size_t)row * K);
    float4 a = p[lane * 2];
    float4 b = p[lane * 2 + 1];
    float s = a.x * a.x + a.y * a.y + a.z * a.z + a.w * a.w
            + b.x * b.x + b.y * b.y + b.z * b.z + b.w * b.w;
    #pragma unroll
    for (int o = 16; o >= 1; o >>= 1)
        s += __shfl_xor_sync(0xffffffffu, s, o);
    if (lane == 0) {
        g_sq[row] = s;
        g_max_eq[row] = 0u;                                 // dist >= 0, diag guarantees non-empty
        g_min_gt[row] = __float_as_uint(BIG);               // sentinel when set empty
        g_min_lt[row] = __float_as_uint(BIG);
        atomicAdd(&g_label_cnt[T[row] & 7], 1);
    }
}

// Fused GEMM: dist tile + per-row hardest-pos/neg stats.
__global__ void __launch_bounds__(256, 2)
k_dist_gemm(const float* __restrict__ X, const int* __restrict__ T,
            float* __restrict__ dist) {
    __shared__ float As[BK][BM];
    __shared__ float Bs[BK][BN];

    const int bm = blockIdx.y * BM;
    const int bn = blockIdx.x * BN;
    const int tid = threadIdx.x;
    const int tx = tid & 15, ty = tid >> 4;

    float acc[TM][TN];
    #pragma unroll
    for (int i = 0; i < TM; ++i)
        #pragma unroll
        for (int j = 0; j < TN; ++j) acc[i][j] = 0.0f;

    for (int k0 = 0; k0 < K; k0 += BK) {
        // 512 float4 per operand tile, 2 per thread per operand
        #pragma unroll
        for (int l = 0; l < 2; ++l) {
            int idx = tid + l * 256;
            int row = idx >> 2;
            int kq  = (idx & 3) << 2;
            float4 va = *reinterpret_cast<const float4*>(&X[(size_t)(bm + row) * K + k0 + kq]);
            As[kq + 0][row] = va.x; As[kq + 1][row] = va.y;
            As[kq + 2][row] = va.z; As[kq + 3][row] = va.w;
            float4 vb = *reinterpret_cast<const float4*>(&X[(size_t)(bn + row) * K + k0 + kq]);
            Bs[kq + 0][row] = vb.x; Bs[kq + 1][row] = vb.y;
            Bs[kq + 2][row] = vb.z; Bs[kq + 3][row] = vb.w;
        }
        __syncthreads();

        #pragma unroll
        for (int k = 0; k < BK; ++k) {
            float a[TM], b[TN];
            *reinterpret_cast<float4*>(&a[0]) = *reinterpret_cast<const float4*>(&As[k][ty * TM]);
            *reinterpret_cast<float4*>(&a[4]) = *reinterpret_cast<const float4*>(&As[k][ty * TM + 4]);
            *reinterpret_cast<float4*>(&b[0]) = *reinterpret_cast<const float4*>(&Bs[k][tx * TN]);
            *reinterpret_cast<float4*>(&b[4]) = *reinterpret_cast<const float4*>(&Bs[k][tx * TN + 4]);
            #pragma unroll
            for (int i = 0; i < TM; ++i)
                #pragma unroll
                for (int j = 0; j < TN; ++j)
                    acc[i][j] = fmaf(a[i], b[j], acc[i][j]);
        }
        __syncthreads();
    }

    // Epilogue: dist + per-row stats
    int   gi[TM], ti[TM];
    float sqi[TM];
    #pragma unroll
    for (int i = 0; i < TM; ++i) {
        gi[i]  = bm + ty * TM + i;
        sqi[i] = g_sq[gi[i]];
        ti[i]  = T[gi[i]];
    }
    int   gj[TN], tj[TN];
    float sqj[TN];
    #pragma unroll
    for (int j = 0; j < TN; ++j) {
        gj[j]  = bn + tx * TN + j;
        sqj[j] = g_sq[gj[j]];
        tj[j]  = T[gj[j]];
    }

    float mx[TM], mg[TM], ml[TM];
    #pragma unroll
    for (int i = 0; i < TM; ++i) { mx[i] = 0.0f; mg[i] = BIG; ml[i] = BIG; }

    #pragma unroll
    for (int i = 0; i < TM; ++i) {
        #pragma unroll
        for (int j = 0; j < TN; ++j) {
            float d2 = sqi[i] + sqj[j] - 2.0f * acc[i][j];
            float d  = sqrtf(fmaxf(d2, 0.0f));
            dist[(size_t)gi[i] * N + gj[j]] = d;
            if (tj[j] == ti[i])      mx[i] = fmaxf(mx[i], d);
            else if (tj[j] > ti[i])  mg[i] = fminf(mg[i], d);
            else                     ml[i] = fminf(ml[i], d);
        }
    }

    // Reduce across the 16 column-threads sharing these rows (xor offsets <= 8
    // stay within the 16-lane half-warp that shares ty)
    #pragma unroll
    for (int o = 8; o >= 1; o >>= 1) {
        #pragma unroll
        for (int i = 0; i < TM; ++i) {
            mx[i] = fmaxf(mx[i], __shfl_xor_sync(0xffffffffu, mx[i], o));
            mg[i] = fminf(mg[i], __shfl_xor_sync(0xffffffffu, mg[i], o));
            ml[i] = fminf(ml[i], __shfl_xor_sync(0xffffffffu, ml[i], o));
        }
    }
    if (tx == 0) {
        #pragma unroll
        for (int i = 0; i < TM; ++i) {
            atomicMax(&g_max_eq[gi[i]], __float_as_uint(mx[i]));
            atomicMin(&g_min_gt[gi[i]], __float_as_uint(mg[i]));
            atomicMin(&g_min_lt[gi[i]], __float_as_uint(ml[i]));
        }
    }
}

__global__ void k_final(const int* __restrict__ T, float* __restrict__ out, int cnt_idx) {
    __shared__ float ssum[1024];
    __shared__ int   scnt[1024];
    int tid = threadIdx.x;
    float s = 0.0f;
    int   c = 0;
    for (int r = tid; r < N; r += 1024) {
        float mx = __uint_as_float(g_max_eq[r]);
        float mg = __uint_as_float(g_min_gt[r]);
        float ml = __uint_as_float(g_min_lt[r]);
        s += fmaxf(mx - fabsf(mg - ml) + MARGIN, 0.0f);
        c += (g_label_cnt[T[r] & 7] == 1) ? 1 : 0;
    }
    ssum[tid] = s; scnt[tid] = c;
    __syncthreads();
    for (int o = 512; o >= 1; o >>= 1) {
        if (tid < o) { ssum[tid] += ssum[tid + o]; scnt[tid] += scnt[tid + o]; }
        __syncthreads();
    }
    if (tid == 0) {
        out[0]       = ssum[0] / (float)N;
        out[cnt_idx] = (float)scnt[0];
    }
}

extern "C" void kernel_launch(void* const* d_in, const int* in_sizes, int n_in,
                              void* d_out, int out_size) {
    const float* X = (const float*)d_in[0];
    const int*   T = (const int*)d_in[1];
    float* out = (float*)d_out;

    k_init_counts<<<1, 32>>>();
    k_sq<<<N / 8, 256>>>(X, T);
    dim3 grid(N / BN, N / BM);
    k_dist_gemm<<<grid, 256>>>(X, T, out + 1);   // dist lives at out[1 .. N*N]
    k_final<<<1, 1024>>>(T, out, out_size - 1);  // loss at out[0], cnt at out[out_size-1]
}

// round 6
// speedup vs baseline: 2.6338x; 2.6338x over previous
#include <cuda_runtime.h>
#include <cuda_bf16.h>
#include <cstdint>

constexpr int N = 4096;
constexpr int K = 256;
constexpr float MARGIN = 0.3f;
constexpr float BIG = 10000.0f;

// ---------------- scratch (device globals; no runtime alloc) ----------------
__device__ __align__(16) float          g_sq[N];
__device__ __align__(16) unsigned       g_max_eq[N];
__device__ __align__(16) unsigned       g_min_gt[N];
__device__ __align__(16) unsigned       g_min_lt[N];
__device__              int             g_label_cnt[8];
__device__ __align__(16) __nv_bfloat16  g_Ah[(size_t)N * K];   // hi bf16
__device__ __align__(16) __nv_bfloat16  g_Al[(size_t)N * K];   // lo bf16 residual

// ---------------- PTX helpers (base ISA only) ----------------
__device__ __forceinline__ uint32_t smem_u32(const void* p) {
    uint32_t a;
    asm("{ .reg .u64 t; cvta.to.shared.u64 t, %1; cvt.u32.u64 %0, t; }" : "=r"(a) : "l"(p));
    return a;
}
__device__ __forceinline__ void cp16(uint32_t saddr, const void* g) {
    asm volatile("cp.async.cg.shared.global [%0], [%1], 16;" :: "r"(saddr), "l"(g));
}
#define CP_COMMIT() asm volatile("cp.async.commit_group;" ::: "memory")
#define CP_WAIT(n)  asm volatile("cp.async.wait_group %0;" :: "n"(n) : "memory")

__device__ __forceinline__ void ldsm4(uint32_t& r0, uint32_t& r1, uint32_t& r2, uint32_t& r3,
                                      uint32_t addr) {
    asm volatile("ldmatrix.sync.aligned.m8n8.x4.shared.b16 {%0,%1,%2,%3}, [%4];"
                 : "=r"(r0), "=r"(r1), "=r"(r2), "=r"(r3) : "r"(addr));
}
__device__ __forceinline__ void mma_bf16(float* d, const uint32_t* a, const uint32_t* b) {
    asm volatile("mma.sync.aligned.m16n8k16.row.col.f32.bf16.bf16.f32 "
                 "{%0,%1,%2,%3},{%4,%5,%6,%7},{%8,%9},{%0,%1,%2,%3};"
                 : "+f"(d[0]), "+f"(d[1]), "+f"(d[2]), "+f"(d[3])
                 : "r"(a[0]), "r"(a[1]), "r"(a[2]), "r"(a[3]), "r"(b[0]), "r"(b[1]));
}

// ---------------- kernels ----------------
__global__ void k_init_counts() {
    if (threadIdx.x < 8) g_label_cnt[threadIdx.x] = 0;
}

// one warp per row: row norm, bf16 hi/lo split, stat init, label histogram
__global__ void k_prep(const float* __restrict__ X, const int* __restrict__ T) {
    int warp = threadIdx.x >> 5, lane = threadIdx.x & 31;
    int row = blockIdx.x * 8 + warp;
    const float4* p = reinterpret_cast<const float4*>(X + (size_t)row * K);
    float4 a = p[lane * 2];
    float4 b = p[lane * 2 + 1];
    float xs[8] = {a.x, a.y, a.z, a.w, b.x, b.y, b.z, b.w};
    float s = 0.0f;
    __nv_bfloat16 hb[8], lb[8];
    #pragma unroll
    for (int e = 0; e < 8; ++e) {
        s = fmaf(xs[e], xs[e], s);
        hb[e] = __float2bfloat16(xs[e]);
        lb[e] = __float2bfloat16(xs[e] - __bfloat162float(hb[e]));
    }
    size_t off = (size_t)row * K + lane * 8;
    *reinterpret_cast<uint4*>(&g_Ah[off]) = *reinterpret_cast<uint4*>(hb);
    *reinterpret_cast<uint4*>(&g_Al[off]) = *reinterpret_cast<uint4*>(lb);
    #pragma unroll
    for (int o = 16; o >= 1; o >>= 1) s += __shfl_xor_sync(0xffffffffu, s, o);
    if (lane == 0) {
        g_sq[row]     = s;
        g_max_eq[row] = 0u;
        g_min_gt[row] = __float_as_uint(BIG);
        g_min_lt[row] = __float_as_uint(BIG);
        atomicAdd(&g_label_cnt[T[row] & 7], 1);
    }
}

// SMEM layout (dynamic):
//   [0] sqj[128]  [512] tj[128]  [1024] sqi[128]  [1536] ti[128]
//   [2048] A0 (16KB)  [18432] B0  [34816] A1  [51200] B1    total 67584
constexpr int SM_SQJ = 0, SM_TJ = 512, SM_SQI = 1024, SM_TI = 1536;
constexpr int SM_A0 = 2048, SM_B0 = 18432, SM_A1 = 34816, SM_B1 = 51200;
constexpr int SMEM_TOTAL = 67584;
constexpr int NUM_KB = 12;   // 3 bf16 segments x (K=256 / BK=64)

__global__ void __launch_bounds__(256)
k_dist_mma(const int* __restrict__ T, float* __restrict__ dist) {
    extern __shared__ char smem[];
    const uint32_t smem_base = smem_u32(smem);
    const int tid  = threadIdx.x;
    const int lane = tid & 31, wid = tid >> 5;
    const int wm = wid & 3, wn = wid >> 2;        // warp tile: 32 rows x 64 cols
    const int bm = blockIdx.y * 128;
    const int bn = blockIdx.x * 128;

    float* sqj = reinterpret_cast<float*>(smem + SM_SQJ);
    int*   tjs = reinterpret_cast<int*>(smem + SM_TJ);
    float* sqi = reinterpret_cast<float*>(smem + SM_SQI);
    int*   tis = reinterpret_cast<int*>(smem + SM_TI);
    if (tid < 128) { sqj[tid] = g_sq[bn + tid]; tjs[tid] = T[bn + tid]; }
    else { int t2 = tid - 128; sqi[t2] = g_sq[bm + t2]; tis[t2] = T[bm + t2]; }

    const int aoff[2] = {SM_A0, SM_A1};
    const int boff[2] = {SM_B0, SM_B1};

    float acc[2][8][4];
    #pragma unroll
    for (int mt = 0; mt < 2; ++mt)
        #pragma unroll
        for (int nt = 0; nt < 8; ++nt)
            #pragma unroll
            for (int e = 0; e < 4; ++e) acc[mt][nt][e] = 0.0f;

    // ---- async load of one double-buffer stage ----
    auto issue = [&](int kb, int s) {
        const char* Asrc = (const char*)((kb < 8) ? g_Ah : g_Al);
        const char* Bsrc = (const char*)((kb >= 4 && kb < 8) ? g_Al : g_Ah);
        const int kq = (kb & 3) * 128;            // byte offset of 64-elem chunk in 512B row
        #pragma unroll
        for (int it = 0; it < 4; ++it) {
            int idx = tid + it * 256;             // 0..1023
            int row = idx >> 3, c = idx & 7;
            uint32_t soff = row * 128 + ((c ^ (row & 7)) * 16);
            cp16(smem_base + aoff[s] + soff, Asrc + (size_t)(bm + row) * 512 + kq + c * 16);
            cp16(smem_base + boff[s] + soff, Bsrc + (size_t)(bn + row) * 512 + kq + c * 16);
        }
    };

    issue(0, 0);
    CP_COMMIT();

    for (int kb = 0; kb < NUM_KB; ++kb) {
        const int s = kb & 1;
        if (kb < NUM_KB - 1) { issue(kb + 1, s ^ 1); CP_COMMIT(); CP_WAIT(1); }
        else CP_WAIT(0);
        __syncthreads();

        const uint32_t ab = smem_base + aoff[s];
        const uint32_t bb = smem_base + boff[s];
        #pragma unroll
        for (int ks = 0; ks < 4; ++ks) {
            const int cb = ks * 2;                // 16B-chunk index of this k16 step
            uint32_t a[2][4];
            #pragma unroll
            for (int mt = 0; mt < 2; ++mt) {
                int row = wm * 32 + mt * 16 + (lane & 15);
                int ch  = (cb + (lane >> 4)) ^ (row & 7);
                ldsm4(a[mt][0], a[mt][1], a[mt][2], a[mt][3], ab + row * 128 + ch * 16);
            }
            uint32_t bf[8][2];
            #pragma unroll
            for (int p = 0; p < 4; ++p) {
                int row = wn * 64 + p * 16 + (lane & 7) + ((lane >> 4) << 3);
                int ch  = (cb + ((lane >> 3) & 1)) ^ (row & 7);
                uint32_t r0, r1, r2, r3;
                ldsm4(r0, r1, r2, r3, bb + row * 128 + ch * 16);
                bf[2 * p][0] = r0; bf[2 * p][1] = r1;
                bf[2 * p + 1][0] = r2; bf[2 * p + 1][1] = r3;
            }
            #pragma unroll
            for (int mt = 0; mt < 2; ++mt)
                #pragma unroll
                for (int nt = 0; nt < 8; ++nt)
                    mma_bf16(acc[mt][nt], a[mt], bf[nt]);
        }
        __syncthreads();
    }

    // ---- epilogue: dist + per-row hardest-pos/neg stats ----
    const int qr = lane >> 2, qc = lane & 3;
    float mx[2][2], mg[2][2], ml[2][2];
    #pragma unroll
    for (int mt = 0; mt < 2; ++mt)
        #pragma unroll
        for (int h = 0; h < 2; ++h) { mx[mt][h] = 0.0f; mg[mt][h] = BIG; ml[mt][h] = BIG; }

    #pragma unroll
    for (int mt = 0; mt < 2; ++mt) {
        #pragma unroll
        for (int h = 0; h < 2; ++h) {
            const int lr   = wm * 32 + mt * 16 + qr + 8 * h;   // row within CTA tile
            const float rs = sqi[lr];
            const int   rt = tis[lr];
            float* drow = dist + (size_t)(bm + lr) * N + bn + wn * 64;
            #pragma unroll
            for (int nt = 0; nt < 8; ++nt) {
                const int c0 = nt * 8 + qc * 2;
                const int lc0 = wn * 64 + c0;
                float d0 = sqrtf(fmaxf(rs + sqj[lc0]     - 2.0f * acc[mt][nt][2 * h + 0], 0.0f));
                float d1 = sqrtf(fmaxf(rs + sqj[lc0 + 1] - 2.0f * acc[mt][nt][2 * h + 1], 0.0f));
                int t0 = tjs[lc0], t1 = tjs[lc0 + 1];
                if (t0 == rt)     mx[mt][h] = fmaxf(mx[mt][h], d0);
                else if (t0 > rt) mg[mt][h] = fminf(mg[mt][h], d0);
                else              ml[mt][h] = fminf(ml[mt][h], d0);
                if (t1 == rt)     mx[mt][h] = fmaxf(mx[mt][h], d1);
                else if (t1 > rt) mg[mt][h] = fminf(mg[mt][h], d1);
                else              ml[mt][h] = fminf(ml[mt][h], d1);
                // scalar stores: dist base is only 4B-aligned (out+1)
                drow[c0]     = d0;
                drow[c0 + 1] = d1;
            }
        }
    }
    // reduce across the 4 lanes (qc) sharing each row
    #pragma unroll
    for (int o = 1; o <= 2; o <<= 1) {
        #pragma unroll
        for (int mt = 0; mt < 2; ++mt)
            #pragma unroll
            for (int h = 0; h < 2; ++h) {
                mx[mt][h] = fmaxf(mx[mt][h], __shfl_xor_sync(0xffffffffu, mx[mt][h], o));
                mg[mt][h] = fminf(mg[mt][h], __shfl_xor_sync(0xffffffffu, mg[mt][h], o));
                ml[mt][h] = fminf(ml[mt][h], __shfl_xor_sync(0xffffffffu, ml[mt][h], o));
            }
    }
    if (qc == 0) {
        #pragma unroll
        for (int mt = 0; mt < 2; ++mt)
            #pragma unroll
            for (int h = 0; h < 2; ++h) {
                int gi = bm + wm * 32 + mt * 16 + qr + 8 * h;
                atomicMax(&g_max_eq[gi], __float_as_uint(mx[mt][h]));
                atomicMin(&g_min_gt[gi], __float_as_uint(mg[mt][h]));
                atomicMin(&g_min_lt[gi], __float_as_uint(ml[mt][h]));
            }
    }
}

__global__ void k_final(const int* __restrict__ T, float* __restrict__ out, int cnt_idx) {
    __shared__ float wsum[32];
    __shared__ int   wcnt[32];
    int tid = threadIdx.x, lane = tid & 31, warp = tid >> 5;
    int r4 = tid * 4;                       // 1024 threads x 4 rows = 4096
    uint4 me = *reinterpret_cast<const uint4*>(&g_max_eq[r4]);
    uint4 gg = *reinterpret_cast<const uint4*>(&g_min_gt[r4]);
    uint4 ll = *reinterpret_cast<const uint4*>(&g_min_lt[r4]);
    int4  tt = *reinterpret_cast<const int4*>(&T[r4]);
    float s = 0.0f; int c = 0;
    {
        unsigned mes[4] = {me.x, me.y, me.z, me.w};
        unsigned ggs[4] = {gg.x, gg.y, gg.z, gg.w};
        unsigned lls[4] = {ll.x, ll.y, ll.z, ll.w};
        int      tts[4] = {tt.x, tt.y, tt.z, tt.w};
        #pragma unroll
        for (int e = 0; e < 4; ++e) {
            float mxv = __uint_as_float(mes[e]);
            float mgv = __uint_as_float(ggs[e]);
            float mlv = __uint_as_float(lls[e]);
            s += fmaxf(mxv - fabsf(mgv - mlv) + MARGIN, 0.0f);
            c += (g_label_cnt[tts[e] & 7] == 1) ? 1 : 0;
        }
    }
    #pragma unroll
    for (int o = 16; o >= 1; o >>= 1) {
        s += __shfl_xor_sync(0xffffffffu, s, o);
        c += __shfl_xor_sync(0xffffffffu, c, o);
    }
    if (lane == 0) { wsum[warp] = s; wcnt[warp] = c; }
    __syncthreads();
    if (warp == 0) {
        s = wsum[lane]; c = wcnt[lane];
        #pragma unroll
        for (int o = 16; o >= 1; o >>= 1) {
            s += __shfl_xor_sync(0xffffffffu, s, o);
            c += __shfl_xor_sync(0xffffffffu, c, o);
        }
        if (lane == 0) { out[0] = s / (float)N; out[cnt_idx] = (float)c; }
    }
}

extern "C" void kernel_launch(void* const* d_in, const int* in_sizes, int n_in,
                              void* d_out, int out_size) {
    const float* X = (const float*)d_in[0];
    const int*   T = (const int*)d_in[1];
    float* out = (float*)d_out;

    static bool attr_done = false;
    if (!attr_done) {
        cudaFuncSetAttribute(k_dist_mma, cudaFuncAttributeMaxDynamicSharedMemorySize, SMEM_TOTAL);
        attr_done = true;
    }

    k_init_counts<<<1, 32>>>();
    k_prep<<<N / 8, 256>>>(X, T);
    dim3 grid(N / 128, N / 128);
    k_dist_mma<<<grid, 256, SMEM_TOTAL>>>(T, out + 1);
    k_final<<<1, 1024>>>(T, out, out_size - 1);
}

// round 7
// speedup vs baseline: 3.2524x; 1.2349x over previous
#include <cuda_runtime.h>
#include <cuda_bf16.h>
#include <cstdint>

constexpr int N = 4096;
constexpr int K = 256;
constexpr float MARGIN = 0.3f;
constexpr float BIG = 10000.0f;

// ---------------- scratch (device globals; no runtime alloc) ----------------
__device__ __align__(16) float          g_sq[N];
__device__ __align__(16) unsigned       g_max_eq[N];
__device__ __align__(16) unsigned       g_min_gt[N];
__device__ __align__(16) unsigned       g_min_lt[N];
__device__              int             g_label_cnt[8];
__device__ __align__(16) __nv_bfloat16  g_Ah[(size_t)N * K];   // hi bf16
__device__ __align__(16) __nv_bfloat16  g_Al[(size_t)N * K];   // lo bf16 residual

// ---------------- PTX helpers (base ISA only) ----------------
__device__ __forceinline__ uint32_t smem_u32(const void* p) {
    uint32_t a;
    asm("{ .reg .u64 t; cvta.to.shared.u64 t, %1; cvt.u32.u64 %0, t; }" : "=r"(a) : "l"(p));
    return a;
}
__device__ __forceinline__ void cp16(uint32_t saddr, const void* g) {
    asm volatile("cp.async.cg.shared.global [%0], [%1], 16;" :: "r"(saddr), "l"(g));
}
#define CP_COMMIT() asm volatile("cp.async.commit_group;" ::: "memory")
#define CP_WAIT(n)  asm volatile("cp.async.wait_group %0;" :: "n"(n) : "memory")

__device__ __forceinline__ void ldsm4(uint32_t& r0, uint32_t& r1, uint32_t& r2, uint32_t& r3,
                                      uint32_t addr) {
    asm volatile("ldmatrix.sync.aligned.m8n8.x4.shared.b16 {%0,%1,%2,%3}, [%4];"
                 : "=r"(r0), "=r"(r1), "=r"(r2), "=r"(r3) : "r"(addr));
}
__device__ __forceinline__ void mma_bf16(float* d, const uint32_t* a, const uint32_t* b) {
    asm volatile("mma.sync.aligned.m16n8k16.row.col.f32.bf16.bf16.f32 "
                 "{%0,%1,%2,%3},{%4,%5,%6,%7},{%8,%9},{%0,%1,%2,%3};"
                 : "+f"(d[0]), "+f"(d[1]), "+f"(d[2]), "+f"(d[3])
                 : "r"(a[0]), "r"(a[1]), "r"(a[2]), "r"(a[3]), "r"(b[0]), "r"(b[1]));
}

// ---------------- kernels ----------------
__global__ void k_init_counts() {
    if (threadIdx.x < 8) g_label_cnt[threadIdx.x] = 0;
}

__global__ void k_prep(const float* __restrict__ X, const int* __restrict__ T) {
    int warp = threadIdx.x >> 5, lane = threadIdx.x & 31;
    int row = blockIdx.x * 8 + warp;
    const float4* p = reinterpret_cast<const float4*>(X + (size_t)row * K);
    float4 a = p[lane * 2];
    float4 b = p[lane * 2 + 1];
    float xs[8] = {a.x, a.y, a.z, a.w, b.x, b.y, b.z, b.w};
    float s = 0.0f;
    __nv_bfloat16 hb[8], lb[8];
    #pragma unroll
    for (int e = 0; e < 8; ++e) {
        s = fmaf(xs[e], xs[e], s);
        hb[e] = __float2bfloat16(xs[e]);
        lb[e] = __float2bfloat16(xs[e] - __bfloat162float(hb[e]));
    }
    size_t off = (size_t)row * K + lane * 8;
    *reinterpret_cast<uint4*>(&g_Ah[off]) = *reinterpret_cast<uint4*>(hb);
    *reinterpret_cast<uint4*>(&g_Al[off]) = *reinterpret_cast<uint4*>(lb);
    #pragma unroll
    for (int o = 16; o >= 1; o >>= 1) s += __shfl_xor_sync(0xffffffffu, s, o);
    if (lane == 0) {
        g_sq[row]     = s;
        g_max_eq[row] = 0u;
        g_min_gt[row] = __float_as_uint(BIG);
        g_min_lt[row] = __float_as_uint(BIG);
        atomicAdd(&g_label_cnt[T[row] & 7], 1);
    }
}

// SMEM layout (dynamic):
//   [0] sqj[128]  [512] tj[128]  [1024] sqi[128]  [1536] ti[128]
//   mainloop:  [2048] A0(16K) [18432] B0 [34816] A1 [51200] B1   (end 67584)
//   epilogue:  [2048] staging tile 128 x 129 floats (66048 B, end 68096)
constexpr int SM_SQJ = 0, SM_TJ = 512, SM_SQI = 1024, SM_TI = 1536;
constexpr int SM_A0 = 2048, SM_B0 = 18432, SM_A1 = 34816, SM_B1 = 51200;
constexpr int SM_TILE = 2048;
constexpr int SMEM_TOTAL = 68096;
constexpr int NUM_KB = 12;   // 3 bf16 segments x (K=256 / BK=64)
constexpr int NBLK = 32;     // 4096/128
constexpr int NTRI = NBLK * (NBLK + 1) / 2;  // 528

__global__ void __launch_bounds__(256)
k_dist_mma(const int* __restrict__ T, float* __restrict__ dist) {
    extern __shared__ char smem[];
    const uint32_t smem_base = smem_u32(smem);
    const int tid  = threadIdx.x;
    const int lane = tid & 31, wid = tid >> 5;
    const int wm = wid & 3, wn = wid >> 2;        // warp tile: 32 rows x 64 cols

    // triangular decode: by >= bx  (bm = row block, bn = col block)
    int idx = blockIdx.x;
    int by = (int)((sqrtf(8.0f * (float)idx + 1.0f) - 1.0f) * 0.5f);
    while ((by + 1) * (by + 2) / 2 <= idx) ++by;
    while (by * (by + 1) / 2 > idx) --by;
    const int bx = idx - by * (by + 1) / 2;
    const int bm = by * 128;
    const int bn = bx * 128;
    const bool diag = (by == bx);

    float* sqj = reinterpret_cast<float*>(smem + SM_SQJ);
    int*   tjs = reinterpret_cast<int*>(smem + SM_TJ);
    float* sqi = reinterpret_cast<float*>(smem + SM_SQI);
    int*   tis = reinterpret_cast<int*>(smem + SM_TI);
    if (tid < 128) { sqj[tid] = g_sq[bn + tid]; tjs[tid] = T[bn + tid]; }
    else { int t2 = tid - 128; sqi[t2] = g_sq[bm + t2]; tis[t2] = T[bm + t2]; }

    const int aoff[2] = {SM_A0, SM_A1};
    const int boff[2] = {SM_B0, SM_B1};

    float acc[2][8][4];
    #pragma unroll
    for (int mt = 0; mt < 2; ++mt)
        #pragma unroll
        for (int nt = 0; nt < 8; ++nt)
            #pragma unroll
            for (int e = 0; e < 4; ++e) acc[mt][nt][e] = 0.0f;

    auto issue = [&](int kb, int s) {
        const char* Asrc = (const char*)((kb < 8) ? g_Ah : g_Al);
        const char* Bsrc = (const char*)((kb >= 4 && kb < 8) ? g_Al : g_Ah);
        const int kq = (kb & 3) * 128;
        #pragma unroll
        for (int it = 0; it < 4; ++it) {
            int idx2 = tid + it * 256;
            int row = idx2 >> 3, c = idx2 & 7;
            uint32_t soff = row * 128 + ((c ^ (row & 7)) * 16);
            cp16(smem_base + aoff[s] + soff, Asrc + (size_t)(bm + row) * 512 + kq + c * 16);
            cp16(smem_base + boff[s] + soff, Bsrc + (size_t)(bn + row) * 512 + kq + c * 16);
        }
    };

    issue(0, 0);
    CP_COMMIT();

    for (int kb = 0; kb < NUM_KB; ++kb) {
        const int s = kb & 1;
        if (kb < NUM_KB - 1) { issue(kb + 1, s ^ 1); CP_COMMIT(); CP_WAIT(1); }
        else CP_WAIT(0);
        __syncthreads();

        const uint32_t ab = smem_base + aoff[s];
        const uint32_t bb = smem_base + boff[s];
        #pragma unroll
        for (int ks = 0; ks < 4; ++ks) {
            const int cb = ks * 2;
            uint32_t a[2][4];
            #pragma unroll
            for (int mt = 0; mt < 2; ++mt) {
                int row = wm * 32 + mt * 16 + (lane & 15);
                int ch  = (cb + (lane >> 4)) ^ (row & 7);
                ldsm4(a[mt][0], a[mt][1], a[mt][2], a[mt][3], ab + row * 128 + ch * 16);
            }
            uint32_t bf[8][2];
            #pragma unroll
            for (int p = 0; p < 4; ++p) {
                int row = wn * 64 + p * 16 + (lane & 7) + ((lane >> 4) << 3);
                int ch  = (cb + ((lane >> 3) & 1)) ^ (row & 7);
                uint32_t r0, r1, r2, r3;
                ldsm4(r0, r1, r2, r3, bb + row * 128 + ch * 16);
                bf[2 * p][0] = r0; bf[2 * p][1] = r1;
                bf[2 * p + 1][0] = r2; bf[2 * p + 1][1] = r3;
            }
            #pragma unroll
            for (int mt = 0; mt < 2; ++mt)
                #pragma unroll
                for (int nt = 0; nt < 8; ++nt)
                    mma_bf16(acc[mt][nt], a[mt], bf[nt]);
        }
        __syncthreads();
    }

    // ---- epilogue ----
    const int qr = lane >> 2, qc = lane & 3;
    float* Tt = reinterpret_cast<float*>(smem + SM_TILE);   // 128 x 129 floats

    float mx[2][2], mg[2][2], ml[2][2];
    #pragma unroll
    for (int mt = 0; mt < 2; ++mt)
        #pragma unroll
        for (int h = 0; h < 2; ++h) { mx[mt][h] = 0.0f; mg[mt][h] = BIG; ml[mt][h] = BIG; }

    #pragma unroll
    for (int mt = 0; mt < 2; ++mt) {
        #pragma unroll
        for (int h = 0; h < 2; ++h) {
            const int lr   = wm * 32 + mt * 16 + qr + 8 * h;
            const float rs = sqi[lr];
            const int   rt = tis[lr];
            float* drow = dist + (size_t)(bm + lr) * N + bn + wn * 64;
            #pragma unroll
            for (int nt = 0; nt < 8; ++nt) {
                const int c0  = nt * 8 + qc * 2;
                const int lc0 = wn * 64 + c0;
                float d0 = sqrtf(fmaxf(rs + sqj[lc0]     - 2.0f * acc[mt][nt][2 * h + 0], 0.0f));
                float d1 = sqrtf(fmaxf(rs + sqj[lc0 + 1] - 2.0f * acc[mt][nt][2 * h + 1], 0.0f));
                int t0 = tjs[lc0], t1 = tjs[lc0 + 1];
                if (t0 == rt)     mx[mt][h] = fmaxf(mx[mt][h], d0);
                else if (t0 > rt) mg[mt][h] = fminf(mg[mt][h], d0);
                else              ml[mt][h] = fminf(ml[mt][h], d0);
                if (t1 == rt)     mx[mt][h] = fmaxf(mx[mt][h], d1);
                else if (t1 > rt) mg[mt][h] = fminf(mg[mt][h], d1);
                else              ml[mt][h] = fminf(ml[mt][h], d1);
                if (diag) {                      // direct store; no staging needed
                    drow[c0]     = d0;
                    drow[c0 + 1] = d1;
                } else {                          // stage for coalesced dual-orientation write
                    Tt[lr * 129 + lc0]     = d0;
                    Tt[lr * 129 + lc0 + 1] = d1;
                }
            }
        }
    }
    // i-row stats: reduce across the 4 qc lanes sharing each row
    #pragma unroll
    for (int o = 1; o <= 2; o <<= 1) {
        #pragma unroll
        for (int mt = 0; mt < 2; ++mt)
            #pragma unroll
            for (int h = 0; h < 2; ++h) {
                mx[mt][h] = fmaxf(mx[mt][h], __shfl_xor_sync(0xffffffffu, mx[mt][h], o));
                mg[mt][h] = fminf(mg[mt][h], __shfl_xor_sync(0xffffffffu, mg[mt][h], o));
                ml[mt][h] = fminf(ml[mt][h], __shfl_xor_sync(0xffffffffu, ml[mt][h], o));
            }
    }
    if (qc == 0) {
        #pragma unroll
        for (int mt = 0; mt < 2; ++mt)
            #pragma unroll
            for (int h = 0; h < 2; ++h) {
                int gi = bm + wm * 32 + mt * 16 + qr + 8 * h;
                atomicMax(&g_max_eq[gi], __float_as_uint(mx[mt][h]));
                atomicMin(&g_min_gt[gi], __float_as_uint(mg[mt][h]));
                atomicMin(&g_min_lt[gi], __float_as_uint(ml[mt][h]));
            }
    }

    if (!diag) {
        __syncthreads();
        // orientation 1: rows of tile -> dist[bm+r][bn..], full-line coalesced
        #pragma unroll
        for (int r0 = 0; r0 < 16; ++r0) {
            const int r = wid * 16 + r0;
            float* drow = dist + (size_t)(bm + r) * N + bn;
            #pragma unroll
            for (int ch = 0; ch < 4; ++ch)
                drow[ch * 32 + lane] = Tt[r * 129 + ch * 32 + lane];
        }
        // orientation 2 + j-row stats: columns of tile -> dist[bn+rp][bm..]
        #pragma unroll
        for (int r0 = 0; r0 < 16; ++r0) {
            const int rp = wid * 16 + r0;           // tile column = output row bn+rp
            const int tc = tjs[rp];
            float jm = 0.0f, jg = BIG, jl = BIG;
            float* drow = dist + (size_t)(bn + rp) * N + bm;
            #pragma unroll
            for (int ch = 0; ch < 4; ++ch) {
                const int i = ch * 32 + lane;       // tile row
                float v = Tt[i * 129 + rp];
                drow[i] = v;
                int rt = tis[i];
                if (rt == tc)     jm = fmaxf(jm, v);
                else if (rt > tc) jg = fminf(jg, v);
                else              jl = fminf(jl, v);
            }
            #pragma unroll
            for (int o = 16; o >= 1; o >>= 1) {
                jm = fmaxf(jm, __shfl_xor_sync(0xffffffffu, jm, o));
                jg = fminf(jg, __shfl_xor_sync(0xffffffffu, jg, o));
                jl = fminf(jl, __shfl_xor_sync(0xffffffffu, jl, o));
            }
            if (lane == 0) {
                atomicMax(&g_max_eq[bn + rp], __float_as_uint(jm));
                atomicMin(&g_min_gt[bn + rp], __float_as_uint(jg));
                atomicMin(&g_min_lt[bn + rp], __float_as_uint(jl));
            }
        }
    }
}

__global__ void k_final(const int* __restrict__ T, float* __restrict__ out, int cnt_idx) {
    __shared__ float wsum[32];
    __shared__ int   wcnt[32];
    int tid = threadIdx.x, lane = tid & 31, warp = tid >> 5;
    int r4 = tid * 4;
    uint4 me = *reinterpret_cast<const uint4*>(&g_max_eq[r4]);
    uint4 gg = *reinterpret_cast<const uint4*>(&g_min_gt[r4]);
    uint4 ll = *reinterpret_cast<const uint4*>(&g_min_lt[r4]);
    int4  tt = *reinterpret_cast<const int4*>(&T[r4]);
    float s = 0.0f; int c = 0;
    {
        unsigned mes[4] = {me.x, me.y, me.z, me.w};
        unsigned ggs[4] = {gg.x, gg.y, gg.z, gg.w};
        unsigned lls[4] = {ll.x, ll.y, ll.z, ll.w};
        int      tts[4] = {tt.x, tt.y, tt.z, tt.w};
        #pragma unroll
        for (int e = 0; e < 4; ++e) {
            float mxv = __uint_as_float(mes[e]);
            float mgv = __uint_as_float(ggs[e]);
            float mlv = __uint_as_float(lls[e]);
            s += fmaxf(mxv - fabsf(mgv - mlv) + MARGIN, 0.0f);
            c += (g_label_cnt[tts[e] & 7] == 1) ? 1 : 0;
        }
    }
    #pragma unroll
    for (int o = 16; o >= 1; o >>= 1) {
        s += __shfl_xor_sync(0xffffffffu, s, o);
        c += __shfl_xor_sync(0xffffffffu, c, o);
    }
    if (lane == 0) { wsum[warp] = s; wcnt[warp] = c; }
    __syncthreads();
    if (warp == 0) {
        s = wsum[lane]; c = wcnt[lane];
        #pragma unroll
        for (int o = 16; o >= 1; o >>= 1) {
            s += __shfl_xor_sync(0xffffffffu, s, o);
            c += __shfl_xor_sync(0xffffffffu, c, o);
        }
        if (lane == 0) { out[0] = s / (float)N; out[cnt_idx] = (float)c; }
    }
}

extern "C" void kernel_launch(void* const* d_in, const int* in_sizes, int n_in,
                              void* d_out, int out_size) {
    const float* X = (const float*)d_in[0];
    const int*   T = (const int*)d_in[1];
    float* out = (float*)d_out;

    static bool attr_done = false;
    if (!attr_done) {
        cudaFuncSetAttribute(k_dist_mma, cudaFuncAttributeMaxDynamicSharedMemorySize, SMEM_TOTAL);
        attr_done = true;
    }

    k_init_counts<<<1, 32>>>();
    k_prep<<<N / 8, 256>>>(X, T);
    k_dist_mma<<<NTRI, 256, SMEM_TOTAL>>>(T, out + 1);
    k_final<<<1, 1024>>>(T, out, out_size - 1);
}

// round 8
// speedup vs baseline: 3.3603x; 1.0332x over previous
#include <cuda_runtime.h>
#include <cuda_bf16.h>
#include <cstdint>

constexpr int N = 4096;
constexpr int K = 256;
constexpr float MARGIN = 0.3f;
constexpr float BIG = 10000.0f;

// ---------------- scratch (device globals; no runtime alloc) ----------------
__device__ __align__(16) float          g_sq[N];
__device__ __align__(16) unsigned       g_max_eq[N];
__device__ __align__(16) unsigned       g_min_gt[N];
__device__ __align__(16) unsigned       g_min_lt[N];
__device__ __align__(16) __nv_bfloat16  g_Ah[(size_t)N * K];   // hi bf16
__device__ __align__(16) __nv_bfloat16  g_Al[(size_t)N * K];   // lo bf16 residual

// ---------------- PTX helpers (base ISA only) ----------------
__device__ __forceinline__ uint32_t smem_u32(const void* p) {
    uint32_t a;
    asm("{ .reg .u64 t; cvta.to.shared.u64 t, %1; cvt.u32.u64 %0, t; }" : "=r"(a) : "l"(p));
    return a;
}
__device__ __forceinline__ void cp16(uint32_t saddr, const void* g) {
    asm volatile("cp.async.cg.shared.global [%0], [%1], 16;" :: "r"(saddr), "l"(g));
}
#define CP_COMMIT() asm volatile("cp.async.commit_group;" ::: "memory")
#define CP_WAIT(n)  asm volatile("cp.async.wait_group %0;" :: "n"(n) : "memory")

__device__ __forceinline__ void ldsm4(uint32_t& r0, uint32_t& r1, uint32_t& r2, uint32_t& r3,
                                      uint32_t addr) {
    asm volatile("ldmatrix.sync.aligned.m8n8.x4.shared.b16 {%0,%1,%2,%3}, [%4];"
                 : "=r"(r0), "=r"(r1), "=r"(r2), "=r"(r3) : "r"(addr));
}
__device__ __forceinline__ void mma_bf16(float* d, const uint32_t* a, const uint32_t* b) {
    asm volatile("mma.sync.aligned.m16n8k16.row.col.f32.bf16.bf16.f32 "
                 "{%0,%1,%2,%3},{%4,%5,%6,%7},{%8,%9},{%0,%1,%2,%3};"
                 : "+f"(d[0]), "+f"(d[1]), "+f"(d[2]), "+f"(d[3])
                 : "r"(a[0]), "r"(a[1]), "r"(a[2]), "r"(a[3]), "r"(b[0]), "r"(b[1]));
}

// ---------------- kernels ----------------
__global__ void k_prep(const float* __restrict__ X, const int* __restrict__ T) {
    int warp = threadIdx.x >> 5, lane = threadIdx.x & 31;
    int row = blockIdx.x * 8 + warp;
    const float4* p = reinterpret_cast<const float4*>(X + (size_t)row * K);
    float4 a = p[lane * 2];
    float4 b = p[lane * 2 + 1];
    float xs[8] = {a.x, a.y, a.z, a.w, b.x, b.y, b.z, b.w};
    float s = 0.0f;
    __nv_bfloat16 hb[8], lb[8];
    #pragma unroll
    for (int e = 0; e < 8; ++e) {
        s = fmaf(xs[e], xs[e], s);
        hb[e] = __float2bfloat16(xs[e]);
        lb[e] = __float2bfloat16(xs[e] - __bfloat162float(hb[e]));
    }
    size_t off = (size_t)row * K + lane * 8;
    *reinterpret_cast<uint4*>(&g_Ah[off]) = *reinterpret_cast<uint4*>(hb);
    *reinterpret_cast<uint4*>(&g_Al[off]) = *reinterpret_cast<uint4*>(lb);
    #pragma unroll
    for (int o = 16; o >= 1; o >>= 1) s += __shfl_xor_sync(0xffffffffu, s, o);
    if (lane == 0) {
        g_sq[row]     = s;
        g_max_eq[row] = 0u;
        g_min_gt[row] = __float_as_uint(BIG);
        g_min_lt[row] = __float_as_uint(BIG);
    }
}

// SMEM layout (dynamic):
//   [0] sqj[128]  [512] tj[128]  [1024] sqi[128]  [1536] ti[128]
//   mainloop:  [2048] A0(16K) [18432] B0 [34816] A1 [51200] B1   (end 67584)
//   epilogue:  [2048] staging tile 128 x 129 floats (66048 B, end 68096)
constexpr int SM_SQJ = 0, SM_TJ = 512, SM_SQI = 1024, SM_TI = 1536;
constexpr int SM_A0 = 2048, SM_B0 = 18432, SM_A1 = 34816, SM_B1 = 51200;
constexpr int SM_TILE = 2048;
constexpr int SMEM_TOTAL = 68096;
constexpr int NUM_KB = 12;   // 3 bf16 segments x (K=256 / BK=64)
constexpr int NBLK = 32;     // 4096/128
constexpr int NTRI = NBLK * (NBLK + 1) / 2;  // 528

__global__ void __launch_bounds__(256, 2)
k_dist_mma(const int* __restrict__ T, float* __restrict__ dist) {
    extern __shared__ char smem[];
    const uint32_t smem_base = smem_u32(smem);
    const int tid  = threadIdx.x;
    const int lane = tid & 31, wid = tid >> 5;
    const int wm = wid & 3, wn = wid >> 2;        // warp tile: 32 rows x 64 cols

    // triangular decode: by >= bx
    int idx = blockIdx.x;
    int by = (int)((sqrtf(8.0f * (float)idx + 1.0f) - 1.0f) * 0.5f);
    while ((by + 1) * (by + 2) / 2 <= idx) ++by;
    while (by * (by + 1) / 2 > idx) --by;
    const int bx = idx - by * (by + 1) / 2;
    const int bm = by * 128;
    const int bn = bx * 128;
    const bool diag = (by == bx);

    float* sqj = reinterpret_cast<float*>(smem + SM_SQJ);
    int*   tjs = reinterpret_cast<int*>(smem + SM_TJ);
    float* sqi = reinterpret_cast<float*>(smem + SM_SQI);
    int*   tis = reinterpret_cast<int*>(smem + SM_TI);
    if (tid < 128) { sqj[tid] = g_sq[bn + tid]; tjs[tid] = T[bn + tid]; }
    else { int t2 = tid - 128; sqi[t2] = g_sq[bm + t2]; tis[t2] = T[bm + t2]; }

    const int aoff[2] = {SM_A0, SM_A1};
    const int boff[2] = {SM_B0, SM_B1};

    float acc[2][8][4];
    #pragma unroll
    for (int mt = 0; mt < 2; ++mt)
        #pragma unroll
        for (int nt = 0; nt < 8; ++nt)
            #pragma unroll
            for (int e = 0; e < 4; ++e) acc[mt][nt][e] = 0.0f;

    auto issue = [&](int kb, int s) {
        const char* Asrc = (const char*)((kb < 8) ? g_Ah : g_Al);
        const char* Bsrc = (const char*)((kb >= 4 && kb < 8) ? g_Al : g_Ah);
        const int kq = (kb & 3) * 128;
        #pragma unroll
        for (int it = 0; it < 4; ++it) {
            int idx2 = tid + it * 256;
            int row = idx2 >> 3, c = idx2 & 7;
            uint32_t soff = row * 128 + ((c ^ (row & 7)) * 16);
            cp16(smem_base + aoff[s] + soff, Asrc + (size_t)(bm + row) * 512 + kq + c * 16);
            cp16(smem_base + boff[s] + soff, Bsrc + (size_t)(bn + row) * 512 + kq + c * 16);
        }
    };

    issue(0, 0);
    CP_COMMIT();

    for (int kb = 0; kb < NUM_KB; ++kb) {
        const int s = kb & 1;
        if (kb < NUM_KB - 1) { issue(kb + 1, s ^ 1); CP_COMMIT(); CP_WAIT(1); }
        else CP_WAIT(0);
        __syncthreads();

        const uint32_t ab = smem_base + aoff[s];
        const uint32_t bb = smem_base + boff[s];
        #pragma unroll
        for (int ks = 0; ks < 4; ++ks) {
            const int cb = ks * 2;
            uint32_t a[2][4];
            #pragma unroll
            for (int mt = 0; mt < 2; ++mt) {
                int row = wm * 32 + mt * 16 + (lane & 15);
                int ch  = (cb + (lane >> 4)) ^ (row & 7);
                ldsm4(a[mt][0], a[mt][1], a[mt][2], a[mt][3], ab + row * 128 + ch * 16);
            }
            uint32_t bf[8][2];
            #pragma unroll
            for (int p = 0; p < 4; ++p) {
                int row = wn * 64 + p * 16 + (lane & 7) + ((lane >> 4) << 3);
                int ch  = (cb + ((lane >> 3) & 1)) ^ (row & 7);
                uint32_t r0, r1, r2, r3;
                ldsm4(r0, r1, r2, r3, bb + row * 128 + ch * 16);
                bf[2 * p][0] = r0; bf[2 * p][1] = r1;
                bf[2 * p + 1][0] = r2; bf[2 * p + 1][1] = r3;
            }
            #pragma unroll
            for (int mt = 0; mt < 2; ++mt)
                #pragma unroll
                for (int nt = 0; nt < 8; ++nt)
                    mma_bf16(acc[mt][nt], a[mt], bf[nt]);
        }
        __syncthreads();
    }

    // ---- epilogue ----
    const int qr = lane >> 2, qc = lane & 3;
    float* Tt = reinterpret_cast<float*>(smem + SM_TILE);   // 128 x 129 floats

    float mx[2][2], mg[2][2], ml[2][2];
    #pragma unroll
    for (int mt = 0; mt < 2; ++mt)
        #pragma unroll
        for (int h = 0; h < 2; ++h) { mx[mt][h] = 0.0f; mg[mt][h] = BIG; ml[mt][h] = BIG; }

    #pragma unroll
    for (int mt = 0; mt < 2; ++mt) {
        #pragma unroll
        for (int h = 0; h < 2; ++h) {
            const int lr   = wm * 32 + mt * 16 + qr + 8 * h;
            const float rs = sqi[lr];
            const int   rt = tis[lr];
            float* drow = dist + (size_t)(bm + lr) * N + bn + wn * 64;
            #pragma unroll
            for (int nt = 0; nt < 8; ++nt) {
                const int c0  = nt * 8 + qc * 2;
                const int lc0 = wn * 64 + c0;
                float d0 = sqrtf(fmaxf(rs + sqj[lc0]     - 2.0f * acc[mt][nt][2 * h + 0], 0.0f));
                float d1 = sqrtf(fmaxf(rs + sqj[lc0 + 1] - 2.0f * acc[mt][nt][2 * h + 1], 0.0f));
                int t0 = tjs[lc0], t1 = tjs[lc0 + 1];
                if (t0 == rt)     mx[mt][h] = fmaxf(mx[mt][h], d0);
                else if (t0 > rt) mg[mt][h] = fminf(mg[mt][h], d0);
                else              ml[mt][h] = fminf(ml[mt][h], d0);
                if (t1 == rt)     mx[mt][h] = fmaxf(mx[mt][h], d1);
                else if (t1 > rt) mg[mt][h] = fminf(mg[mt][h], d1);
                else              ml[mt][h] = fminf(ml[mt][h], d1);
                if (diag) {
                    drow[c0]     = d0;
                    drow[c0 + 1] = d1;
                } else {
                    Tt[lr * 129 + lc0]     = d0;
                    Tt[lr * 129 + lc0 + 1] = d1;
                }
            }
        }
    }
    #pragma unroll
    for (int o = 1; o <= 2; o <<= 1) {
        #pragma unroll
        for (int mt = 0; mt < 2; ++mt)
            #pragma unroll
            for (int h = 0; h < 2; ++h) {
                mx[mt][h] = fmaxf(mx[mt][h], __shfl_xor_sync(0xffffffffu, mx[mt][h], o));
                mg[mt][h] = fminf(mg[mt][h], __shfl_xor_sync(0xffffffffu, mg[mt][h], o));
                ml[mt][h] = fminf(ml[mt][h], __shfl_xor_sync(0xffffffffu, ml[mt][h], o));
            }
    }
    if (qc == 0) {
        #pragma unroll
        for (int mt = 0; mt < 2; ++mt)
            #pragma unroll
            for (int h = 0; h < 2; ++h) {
                int gi = bm + wm * 32 + mt * 16 + qr + 8 * h;
                atomicMax(&g_max_eq[gi], __float_as_uint(mx[mt][h]));
                atomicMin(&g_min_gt[gi], __float_as_uint(mg[mt][h]));
                atomicMin(&g_min_lt[gi], __float_as_uint(ml[mt][h]));
            }
    }

    if (!diag) {
        __syncthreads();
        // orientation 1: rows of tile -> dist[bm+r][bn..]
        #pragma unroll
        for (int r0 = 0; r0 < 16; ++r0) {
            const int r = wid * 16 + r0;
            float* drow = dist + (size_t)(bm + r) * N + bn;
            #pragma unroll
            for (int ch = 0; ch < 4; ++ch)
                drow[ch * 32 + lane] = Tt[r * 129 + ch * 32 + lane];
        }
        // orientation 2 + j-row stats
        #pragma unroll
        for (int r0 = 0; r0 < 16; ++r0) {
            const int rp = wid * 16 + r0;
            const int tc = tjs[rp];
            float jm = 0.0f, jg = BIG, jl = BIG;
            float* drow = dist + (size_t)(bn + rp) * N + bm;
            #pragma unroll
            for (int ch = 0; ch < 4; ++ch) {
                const int i = ch * 32 + lane;
                float v = Tt[i * 129 + rp];
                drow[i] = v;
                int rt = tis[i];
                if (rt == tc)     jm = fmaxf(jm, v);
                else if (rt > tc) jg = fminf(jg, v);
                else              jl = fminf(jl, v);
            }
            #pragma unroll
            for (int o = 16; o >= 1; o >>= 1) {
                jm = fmaxf(jm, __shfl_xor_sync(0xffffffffu, jm, o));
                jg = fminf(jg, __shfl_xor_sync(0xffffffffu, jg, o));
                jl = fminf(jl, __shfl_xor_sync(0xffffffffu, jl, o));
            }
            if (lane == 0) {
                atomicMax(&g_max_eq[bn + rp], __float_as_uint(jm));
                atomicMin(&g_min_gt[bn + rp], __float_as_uint(jg));
                atomicMin(&g_min_lt[bn + rp], __float_as_uint(jl));
            }
        }
    }
}

__global__ void k_final(const int* __restrict__ T, float* __restrict__ out, int cnt_idx) {
    __shared__ float wsum[32];
    __shared__ int   wcnt[32];
    __shared__ int   hist[4];
    int tid = threadIdx.x, lane = tid & 31, warp = tid >> 5;
    if (tid < 4) hist[tid] = 0;
    __syncthreads();
    int r4 = tid * 4;
    int4  tt = *reinterpret_cast<const int4*>(&T[r4]);
    int tts[4] = {tt.x, tt.y, tt.z, tt.w};
    // warp-level label histogram, then one smem atomic per warp per bin
    #pragma unroll
    for (int b = 0; b < 4; ++b) {
        int m = ((tts[0] == b) ? 1 : 0) + ((tts[1] == b) ? 1 : 0)
              + ((tts[2] == b) ? 1 : 0) + ((tts[3] == b) ? 1 : 0);
        #pragma unroll
        for (int o = 16; o >= 1; o >>= 1) m += __shfl_xor_sync(0xffffffffu, m, o);
        if (lane == 0) atomicAdd(&hist[b], m);
    }
    uint4 me = *reinterpret_cast<const uint4*>(&g_max_eq[r4]);
    uint4 gg = *reinterpret_cast<const uint4*>(&g_min_gt[r4]);
    uint4 ll = *reinterpret_cast<const uint4*>(&g_min_lt[r4]);
    __syncthreads();
    float s = 0.0f; int c = 0;
    {
        unsigned mes[4] = {me.x, me.y, me.z, me.w};
        unsigned ggs[4] = {gg.x, gg.y, gg.z, gg.w};
        unsigned lls[4] = {ll.x, ll.y, ll.z, ll.w};
        #pragma unroll
        for (int e = 0; e < 4; ++e) {
            float mxv = __uint_as_float(mes[e]);
            float mgv = __uint_as_float(ggs[e]);
            float mlv = __uint_as_float(lls[e]);
            s += fmaxf(mxv - fabsf(mgv - mlv) + MARGIN, 0.0f);
            c += (hist[tts[e] & 3] == 1) ? 1 : 0;
        }
    }
    #pragma unroll
    for (int o = 16; o >= 1; o >>= 1) {
        s += __shfl_xor_sync(0xffffffffu, s, o);
        c += __shfl_xor_sync(0xffffffffu, c, o);
    }
    if (lane == 0) { wsum[warp] = s; wcnt[warp] = c; }
    __syncthreads();
    if (warp == 0) {
        s = wsum[lane]; c = wcnt[lane];
        #pragma unroll
        for (int o = 16; o >= 1; o >>= 1) {
            s += __shfl_xor_sync(0xffffffffu, s, o);
            c += __shfl_xor_sync(0xffffffffu, c, o);
        }
        if (lane == 0) { out[0] = s / (float)N; out[cnt_idx] = (float)c; }
    }
}

extern "C" void kernel_launch(void* const* d_in, const int* in_sizes, int n_in,
                              void* d_out, int out_size) {
    const float* X = (const float*)d_in[0];
    const int*   T = (const int*)d_in[1];
    float* out = (float*)d_out;

    static bool attr_done = false;
    if (!attr_done) {
        cudaFuncSetAttribute(k_dist_mma, cudaFuncAttributeMaxDynamicSharedMemorySize, SMEM_TOTAL);
        attr_done = true;
    }

    k_prep<<<N / 8, 256>>>(X, T);
    k_dist_mma<<<NTRI, 256, SMEM_TOTAL>>>(T, out + 1);
    k_final<<<1, 1024>>>(T, out, out_size - 1);
}